// round 10
// baseline (speedup 1.0000x reference)
#include <cuda_runtime.h>
#include <cuda_fp16.h>
#include <cstdint>

#define N_NODES 8192
#define ALPHA   0.2f

// ---------------- scratch (device globals; no allocations allowed) ----------
__device__ float  g_bufA[N_NODES * 128];
__device__ float  g_bufB[N_NODES * 128];
__device__ __half g_hT [128 * N_NODES];
__device__ float  g_src[N_NODES];
__device__ float  g_dst[N_NODES];
__device__ float  g_zA [N_NODES];
__device__ float  g_zB [N_NODES];
__device__ float  g_gmax[1];

__device__ __forceinline__ float leaky(float x) { return x >= 0.f ? x : ALPHA * x; }

// pack two f32 -> one u32 holding f16x2 (single cvt.rn.f16x2 SASS op)
__device__ __forceinline__ unsigned pack_h2(float lo, float hi) {
    unsigned r;
    asm("cvt.rn.f16x2.f32 %0, %1, %2;" : "=r"(r) : "f"(hi), "f"(lo));
    return r;
}

// ---------------------------------------------------------------------------
// mma.sync helpers (base-ISA HMMA path; validated in rounds 6-7)
// ---------------------------------------------------------------------------
__device__ __forceinline__ void ldsm_x4(unsigned& r0, unsigned& r1,
                                        unsigned& r2, unsigned& r3, unsigned a) {
    asm volatile("ldmatrix.sync.aligned.m8n8.x4.shared.b16 {%0,%1,%2,%3}, [%4];"
                 : "=r"(r0), "=r"(r1), "=r"(r2), "=r"(r3) : "r"(a));
}
__device__ __forceinline__ void mma16816(float* d,
                                         unsigned a0, unsigned a1, unsigned a2, unsigned a3,
                                         unsigned b0, unsigned b1) {
    asm volatile(
        "mma.sync.aligned.m16n8k16.row.col.f32.f16.f16.f32 "
        "{%0,%1,%2,%3}, {%4,%5,%6,%7}, {%8,%9}, {%0,%1,%2,%3};"
        : "+f"(d[0]), "+f"(d[1]), "+f"(d[2]), "+f"(d[3])
        : "r"(a0), "r"(a1), "r"(a2), "r"(a3), "r"(b0), "r"(b1));
}

// ===========================================================================
// Fused MLP (4 layers) via HMMA, one kernel, 64 rows/block, grid 128.
// ===========================================================================
#define SW 280
#define WT_BYTES  (128 * SW * 2)
#define ACT_BYTES (64 * SW * 2)
#define MLP_SMEM  (WT_BYTES + 2 * ACT_BYTES)

struct Frag { float a[8][4]; };

__device__ __forceinline__ void mlp_mma(Frag& fr, unsigned inA, unsigned WT,
                                        int K, int wrow, int wcol, int lane)
{
    const unsigned a_base = inA + ((unsigned)(wrow + (lane & 15)) * SW
                          + (unsigned)((lane >> 4) * 8)) * 2;
    const unsigned b_base = WT + ((unsigned)(wcol + (lane & 7) + ((lane >> 4) << 3)) * SW
                          + (unsigned)(((lane >> 3) & 1) << 3)) * 2;
#pragma unroll 4
    for (int ks = 0; ks < K / 16; ks++) {
        unsigned a0, a1, a2, a3;
        ldsm_x4(a0, a1, a2, a3, a_base + (unsigned)ks * 32);
#pragma unroll
        for (int nb = 0; nb < 4; nb++) {
            unsigned b0, b1, b2, b3;
            ldsm_x4(b0, b1, b2, b3,
                    b_base + (unsigned)nb * 16 * SW * 2 + (unsigned)ks * 32);
            mma16816(fr.a[nb * 2],     a0, a1, a2, a3, b0, b1);
            mma16816(fr.a[nb * 2 + 1], a0, a1, a2, a3, b2, b3);
        }
    }
}

__device__ __forceinline__ void load_W(unsigned WT, const float* __restrict__ Wg,
                                       int K, int tid)
{
    const int total = K * 128;
#pragma unroll 8
    for (int i = 0; i < total / 256; i++) {
        int idx = tid + i * 256;
        int k = idx >> 7, n = idx & 127;
        unsigned short hw = __half_as_ushort(__float2half_rn(Wg[idx]));
        unsigned ad = WT + ((unsigned)n * SW + (unsigned)k) * 2;
        asm volatile("st.shared.u16 [%0], %1;" :: "r"(ad), "h"(hw));
    }
}

__global__ void __launch_bounds__(256) mlp_kernel(
    const float* __restrict__ nodes,
    const float* __restrict__ W1, const float* __restrict__ b1,
    const float* __restrict__ W2, const float* __restrict__ b2,
    const float* __restrict__ W3, const float* __restrict__ b3,
    const float* __restrict__ W4, const float* __restrict__ b4,
    const float* __restrict__ a_w,
    __half* __restrict__ hT, float* __restrict__ s_src, float* __restrict__ s_dst)
{
    extern __shared__ char sm[];
    const unsigned smb = (unsigned)__cvta_generic_to_shared(sm);
    const unsigned WT = smb;
    const unsigned A0 = smb + WT_BYTES;
    const unsigned A1 = A0 + ACT_BYTES;

    const int tid = threadIdx.x, wid = tid >> 5, lane = tid & 31;
    const int r0 = blockIdx.x * 64;
    const int wrow = (wid & 3) * 16;
    const int wcol = (wid >> 2) * 64;

    // ---- load x (64 x 256 f32) -> act0 fp16 ----
#pragma unroll
    for (int i = 0; i < 16; i++) {
        int idx = tid + i * 256;
        int r = idx >> 6, c4 = (idx & 63) << 2;
        float4 v = *reinterpret_cast<const float4*>(&nodes[(size_t)(r0 + r) * 256 + c4]);
        unsigned h01 = pack_h2(v.x, v.y);
        unsigned h23 = pack_h2(v.z, v.w);
        unsigned ad = A0 + ((unsigned)r * SW + (unsigned)c4) * 2;
        asm volatile("st.shared.v2.b32 [%0], {%1,%2};" :: "r"(ad), "r"(h01), "r"(h23));
    }

    // =============== layers 1-3 (relu) ===============
    const float* Ws[3] = { W1, W2, W3 };
    const float* bs[3] = { b1, b2, b3 };
#pragma unroll 1
    for (int l = 0; l < 3; l++) {
        const int K = (l == 0) ? 256 : 128;
        const unsigned inA  = (l & 1) ? A1 : A0;
        const unsigned outA = (l & 1) ? A0 : A1;
        load_W(WT, Ws[l], K, tid);
        __syncthreads();                     // W + act visible
        Frag fr;
#pragma unroll
        for (int f = 0; f < 8; f++)
#pragma unroll
            for (int c = 0; c < 4; c++) fr.a[f][c] = 0.f;
        mlp_mma(fr, inA, WT, K, wrow, wcol, lane);
        __syncthreads();                     // all mma done before W overwrite
        // epilogue: bias + relu -> fp16 act
        const float* bias = bs[l];
        const int r1 = wrow + (lane >> 2);
#pragma unroll
        for (int f = 0; f < 8; f++) {
            int n0 = wcol + f * 8 + (lane & 3) * 2;
            float bx = bias[n0], by = bias[n0 + 1];
            float v0 = fmaxf(fr.a[f][0] + bx, 0.f);
            float v1 = fmaxf(fr.a[f][1] + by, 0.f);
            float v2 = fmaxf(fr.a[f][2] + bx, 0.f);
            float v3 = fmaxf(fr.a[f][3] + by, 0.f);
            unsigned p0 = pack_h2(v0, v1);
            unsigned p1 = pack_h2(v2, v3);
            unsigned ad0 = outA + ((unsigned)r1 * SW + (unsigned)n0) * 2;
            unsigned ad1 = outA + ((unsigned)(r1 + 8) * SW + (unsigned)n0) * 2;
            asm volatile("st.shared.u32 [%0], %1;" :: "r"(ad0), "r"(p0));
            asm volatile("st.shared.u32 [%0], %1;" :: "r"(ad1), "r"(p1));
        }
    }

    // =============== layer 4 (no relu) + fused scores + h store ===============
    load_W(WT, W4, 128, tid);
    __syncthreads();
    Frag fr;
#pragma unroll
    for (int f = 0; f < 8; f++)
#pragma unroll
        for (int c = 0; c < 4; c++) fr.a[f][c] = 0.f;
    mlp_mma(fr, A1, WT, 128, wrow, wcol, lane);   // layer3 out = A1
    __syncthreads();

    const int r1 = wrow + (lane >> 2);
    float p1a = 0.f, p1b = 0.f, p2a = 0.f, p2b = 0.f;  // (src,dst) x (r1, r1+8)
#pragma unroll
    for (int f = 0; f < 8; f++) {
        int n0 = wcol + f * 8 + (lane & 3) * 2;
        float bx = b4[n0], by = b4[n0 + 1];
        float a1x = a_w[n0],       a1y = a_w[n0 + 1];
        float a2x = a_w[128 + n0], a2y = a_w[128 + n0 + 1];
        float v0 = fr.a[f][0] + bx, v1 = fr.a[f][1] + by;
        float v2 = fr.a[f][2] + bx, v3 = fr.a[f][3] + by;
        p1a += v0 * a1x + v1 * a1y;  p1b += v0 * a2x + v1 * a2y;
        p2a += v2 * a1x + v3 * a1y;  p2b += v2 * a2x + v3 * a2y;
        unsigned q0 = pack_h2(v0, v1);
        unsigned q1 = pack_h2(v2, v3);
        unsigned ad0 = A0 + ((unsigned)r1 * SW + (unsigned)n0) * 2;
        unsigned ad1 = A0 + ((unsigned)(r1 + 8) * SW + (unsigned)n0) * 2;
        asm volatile("st.shared.u32 [%0], %1;" :: "r"(ad0), "r"(q0));
        asm volatile("st.shared.u32 [%0], %1;" :: "r"(ad1), "r"(q1));
    }
    // reduce score partials over the 4 lanes sharing a row
#pragma unroll
    for (int o = 1; o < 4; o <<= 1) {
        p1a += __shfl_xor_sync(0xffffffffu, p1a, o);
        p1b += __shfl_xor_sync(0xffffffffu, p1b, o);
        p2a += __shfl_xor_sync(0xffffffffu, p2a, o);
        p2b += __shfl_xor_sync(0xffffffffu, p2b, o);
    }
    // per-(row, colgroup) partials -> A1 region (free now)
    const int cg = wid >> 2;
    if ((lane & 3) == 0) {
        unsigned s0 = A1 + (unsigned)((r1 * 2 + cg) * 4);
        unsigned s1 = A1 + (unsigned)(((r1 + 8) * 2 + cg) * 4);
        unsigned d0 = A1 + 1024u + (unsigned)((r1 * 2 + cg) * 4);
        unsigned d1 = A1 + 1024u + (unsigned)(((r1 + 8) * 2 + cg) * 4);
        asm volatile("st.shared.f32 [%0], %1;" :: "r"(s0), "f"(p1a));
        asm volatile("st.shared.f32 [%0], %1;" :: "r"(s1), "f"(p2a));
        asm volatile("st.shared.f32 [%0], %1;" :: "r"(d0), "f"(p1b));
        asm volatile("st.shared.f32 [%0], %1;" :: "r"(d1), "f"(p2b));
    }
    __syncthreads();

    if (tid < 64) {
        float sa, sb, da, db;
        unsigned base = A1 + (unsigned)(tid * 8);
        asm volatile("ld.shared.f32 %0, [%1];"      : "=f"(sa) : "r"(base));
        asm volatile("ld.shared.f32 %0, [%1+4];"    : "=f"(sb) : "r"(base));
        asm volatile("ld.shared.f32 %0, [%1+1024];" : "=f"(da) : "r"(base));
        asm volatile("ld.shared.f32 %0, [%1+1028];" : "=f"(db) : "r"(base));
        s_src[r0 + tid] = sa + sb;
        s_dst[r0 + tid] = da + db;
    }

    // ---- hT[c][r0 + seg*32 .. +31] from h fp16 in A0 ----
    // thread -> (c = tid&127, seg = tid>>7); 32 rows per thread = 16 packed u32
    {
        int c = tid & 127, seg = tid >> 7;
        unsigned r16[16];
#pragma unroll
        for (int u = 0; u < 16; u++) {
            unsigned short h0, h1;
            unsigned ad = A0 + ((unsigned)(seg * 32 + u * 2) * SW + (unsigned)c) * 2;
            asm volatile("ld.shared.u16 %0, [%1];" : "=h"(h0) : "r"(ad));
            asm volatile("ld.shared.u16 %0, [%1];" : "=h"(h1) : "r"(ad + SW * 2));
            r16[u] = (unsigned)h0 | ((unsigned)h1 << 16);
        }
        uint4* dst = reinterpret_cast<uint4*>(&hT[(size_t)c * N_NODES + r0 + seg * 32]);
        dst[0] = make_uint4(r16[0],  r16[1],  r16[2],  r16[3]);
        dst[1] = make_uint4(r16[4],  r16[5],  r16[6],  r16[7]);
        dst[2] = make_uint4(r16[8],  r16[9],  r16[10], r16[11]);
        dst[3] = make_uint4(r16[12], r16[13], r16[14], r16[15]);
    }
}

// ---------------------------------------------------------------------------
// gmax
// ---------------------------------------------------------------------------
__global__ void __launch_bounds__(256) gmax_kernel(
    const float* __restrict__ s_dst, float* __restrict__ out)
{
    __shared__ float red[256];
    float m = -1e30f;
    for (int i = threadIdx.x; i < N_NODES; i += 256)
        m = fmaxf(m, s_dst[i]);
    red[threadIdx.x] = m;
    __syncthreads();
    for (int s = 128; s; s >>= 1) {
        if (threadIdx.x < s) red[threadIdx.x] = fmaxf(red[threadIdx.x], red[threadIdx.x + s]);
        __syncthreads();
    }
    if (threadIdx.x == 0) out[0] = red[0];
}

// ---------------------------------------------------------------------------
// Fused attention via dense HMMA (unchanged from round 7 — passing)
// ---------------------------------------------------------------------------
#define NTILES 32
#define LDH 136
#define HT_BYTES (128 * LDH * 2)
#define ATTN_SMEM (4 * HT_BYTES)

__global__ void __launch_bounds__(512, 1) attn_kernel(
    const float* __restrict__ adj, const __half* __restrict__ hTg,
    const float* __restrict__ s_src, const float* __restrict__ s_dst,
    const float* __restrict__ p_ab, const float* __restrict__ p_gmax,
    float* __restrict__ accA, float* __restrict__ accB,
    float* __restrict__ zA, float* __restrict__ zB)
{
    extern __shared__ char sm[];
    const unsigned smb = (unsigned)__cvta_generic_to_shared(sm);
    const unsigned HT0 = smb, HT1 = smb + HT_BYTES;
    const unsigned P0 = smb + 2 * HT_BYTES, P1 = smb + 3 * HT_BYTES;

    const int tid = threadIdx.x, wid = tid >> 5, lane = tid & 31;
    const int half = blockIdx.x, r0 = blockIdx.y * 128;
    const int j0 = half * (N_NODES / 2);
    float* accbuf = half ? accB : accA;
    float* zbuf   = half ? zB  : zA;

    const float ab   = *p_ab;
    const float gmax = *p_gmax;

    float si8[8], mi8[8], zv[8];
#pragma unroll
    for (int v = 0; v < 8; v++) {
        float sv = s_src[r0 + 8 * wid + v];
        si8[v] = sv;
        mi8[v] = leaky(sv + ab + gmax);
        zv[v] = 0.f;
    }

    const int wrow = (wid & 7) * 16;
    const int wcol = (wid >> 3) * 64;
    const unsigned a_off = (unsigned)(wrow + (lane & 15)) * (LDH * 2)
                         + (unsigned)((lane >> 4) * 8) * 2;
    const unsigned b_off = (unsigned)(wcol + (lane & 7) + ((lane >> 4) << 3)) * (LDH * 2)
                         + (unsigned)(((lane >> 3) & 1) << 3) * 2;

    float acc[8][4];
#pragma unroll
    for (int f = 0; f < 8; f++)
#pragma unroll
        for (int c = 0; c < 4; c++) acc[f][c] = 0.f;

    const float* abase = adj + (size_t)(r0 + 8 * wid) * N_NODES + j0 + lane * 4;

    auto load_hT = [&](int tile, unsigned Hb) {
#pragma unroll
        for (int i = 0; i < 4; i++) {
            int ch = tid + i * 512;
            int c = ch >> 4, u = ch & 15;
            const __half* src = hTg + (size_t)c * N_NODES + j0 + tile * 128 + u * 8;
            unsigned ad = Hb + (unsigned)c * (LDH * 2) + (unsigned)u * 16;
            asm volatile("cp.async.ca.shared.global [%0], [%1], 16;"
                         :: "r"(ad), "l"(src));
        }
    };

    float4 av[8];
    load_hT(0, HT0);
    asm volatile("cp.async.commit_group;" ::: "memory");
#pragma unroll
    for (int v = 0; v < 8; v++)
        av[v] = *reinterpret_cast<const float4*>(abase + (size_t)v * N_NODES);

    for (int k = 0; k < NTILES; k++) {
        const unsigned Pb = (k & 1) ? P1 : P0;
        const unsigned Hb = (k & 1) ? HT1 : HT0;

        float4 t = *reinterpret_cast<const float4*>(s_dst + j0 + k * 128 + lane * 4);
#pragma unroll
        for (int v = 0; v < 8; v++) {
            float4 a = av[v];
            unsigned lo = 0u, hi = 0u;
            if (a.x >= 0.5f) { float w = __expf(leaky(si8[v] + t.x + ab) - mi8[v]);
                zv[v] += w; lo  = (unsigned)__half_as_ushort(__float2half_rn(w)); }
            if (a.y >= 0.5f) { float w = __expf(leaky(si8[v] + t.y + ab) - mi8[v]);
                zv[v] += w; lo |= (unsigned)__half_as_ushort(__float2half_rn(w)) << 16; }
            if (a.z >= 0.5f) { float w = __expf(leaky(si8[v] + t.z + ab) - mi8[v]);
                zv[v] += w; hi  = (unsigned)__half_as_ushort(__float2half_rn(w)); }
            if (a.w >= 0.5f) { float w = __expf(leaky(si8[v] + t.w + ab) - mi8[v]);
                zv[v] += w; hi |= (unsigned)__half_as_ushort(__float2half_rn(w)) << 16; }
            unsigned ad = Pb + (unsigned)(8 * wid + v) * (LDH * 2) + (unsigned)lane * 8;
            asm volatile("st.shared.v2.b32 [%0], {%1,%2};"
                         :: "r"(ad), "r"(lo), "r"(hi) : "memory");
        }

        asm volatile("cp.async.wait_group 0;" ::: "memory");
        __syncthreads();

        if (k + 1 < NTILES) {
            load_hT(k + 1, (k & 1) ? HT0 : HT1);
            asm volatile("cp.async.commit_group;" ::: "memory");
#pragma unroll
            for (int v = 0; v < 8; v++)
                av[v] = *reinterpret_cast<const float4*>(
                    abase + (size_t)v * N_NODES + (k + 1) * 128);
        }

#pragma unroll
        for (int ks = 0; ks < 8; ks++) {
            unsigned a0, a1, a2, a3;
            ldsm_x4(a0, a1, a2, a3, Pb + a_off + (unsigned)ks * 32);
#pragma unroll
            for (int nb = 0; nb < 4; nb++) {
                unsigned b0, b1, b2, b3;
                ldsm_x4(b0, b1, b2, b3,
                        Hb + b_off + (unsigned)nb * 16 * (LDH * 2) + (unsigned)ks * 32);
                mma16816(acc[nb * 2],     a0, a1, a2, a3, b0, b1);
                mma16816(acc[nb * 2 + 1], a0, a1, a2, a3, b2, b3);
            }
        }
    }

#pragma unroll
    for (int f = 0; f < 8; f++) {
        int n0 = wcol + f * 8 + (lane & 3) * 2;
        int rr = r0 + wrow + (lane >> 2);
        *reinterpret_cast<float2*>(&accbuf[(size_t)rr * 128 + n0]) =
            make_float2(acc[f][0], acc[f][1]);
        *reinterpret_cast<float2*>(&accbuf[(size_t)(rr + 8) * 128 + n0]) =
            make_float2(acc[f][2], acc[f][3]);
    }
#pragma unroll
    for (int v = 0; v < 8; v++) {
        float zz = zv[v];
#pragma unroll
        for (int o = 16; o; o >>= 1)
            zz += __shfl_xor_sync(0xffffffffu, zz, o);
        if (lane == 0) zbuf[r0 + 8 * wid + v] = zz;
    }
}

// ---------------------------------------------------------------------------
// out = leaky((accA + accB) / (zA + zB))
// ---------------------------------------------------------------------------
__global__ void __launch_bounds__(256) combine_kernel(
    const float* __restrict__ a, const float* __restrict__ b,
    const float* __restrict__ za, const float* __restrict__ zb,
    float* __restrict__ out)
{
    int idx = blockIdx.x * 256 + threadIdx.x;
    int row = idx >> 5;
    float inv = 1.f / (za[row] + zb[row]);
    float4 x = reinterpret_cast<const float4*>(a)[idx];
    float4 y = reinterpret_cast<const float4*>(b)[idx];
    float4 o;
    o.x = leaky((x.x + y.x) * inv);
    o.y = leaky((x.y + y.y) * inv);
    o.z = leaky((x.z + y.z) * inv);
    o.w = leaky((x.w + y.w) * inv);
    reinterpret_cast<float4*>(out)[idx] = o;
}

// ---------------------------------------------------------------------------
extern "C" void kernel_launch(void* const* d_in, const int* in_sizes, int n_in,
                              void* d_out, int out_size)
{
    const float* nodes = (const float*)d_in[0];
    const float* adj   = (const float*)d_in[1];
    const float* W1    = (const float*)d_in[2];
    const float* b1    = (const float*)d_in[3];
    const float* W2    = (const float*)d_in[4];
    const float* b2    = (const float*)d_in[5];
    const float* W3    = (const float*)d_in[6];
    const float* b3    = (const float*)d_in[7];
    const float* W4    = (const float*)d_in[8];
    const float* b4    = (const float*)d_in[9];
    const float* a_w   = (const float*)d_in[10];
    const float* a_b   = (const float*)d_in[11];
    float* out = (float*)d_out;

    float *pA, *pB, *pSrc, *pDst, *pZA, *pZB, *pGM;
    __half* pHT;
    cudaGetSymbolAddress((void**)&pA,  g_bufA);
    cudaGetSymbolAddress((void**)&pB,  g_bufB);
    cudaGetSymbolAddress((void**)&pHT, g_hT);
    cudaGetSymbolAddress((void**)&pSrc, g_src);
    cudaGetSymbolAddress((void**)&pDst, g_dst);
    cudaGetSymbolAddress((void**)&pZA, g_zA);
    cudaGetSymbolAddress((void**)&pZB, g_zB);
    cudaGetSymbolAddress((void**)&pGM, g_gmax);

    cudaFuncSetAttribute(mlp_kernel,
                         cudaFuncAttributeMaxDynamicSharedMemorySize, MLP_SMEM);
    cudaFuncSetAttribute(attn_kernel,
                         cudaFuncAttributeMaxDynamicSharedMemorySize, ATTN_SMEM);

    // fused 4-layer MLP + scores + hT
    mlp_kernel<<<128, 256, MLP_SMEM>>>(nodes, W1, b1, W2, b2, W3, b3, W4, b4,
                                       a_w, pHT, pSrc, pDst);
    // global max bound
    gmax_kernel<<<1, 256>>>(pDst, pGM);
    // fused attention via dense HMMA
    dim3 agrid(2, 64);
    attn_kernel<<<agrid, 512, ATTN_SMEM>>>(
        adj, pHT, pSrc, pDst, a_b, pGM, pA, pB, pZA, pZB);
    // normalize + activation
    combine_kernel<<<1024, 256>>>(pA, pB, pZA, pZB, out);
}

// round 11
// speedup vs baseline: 1.3482x; 1.3482x over previous
#include <cuda_runtime.h>
#include <cuda_fp16.h>
#include <cstdint>

#define N_NODES 8192
#define ALPHA   0.2f

// ---------------- scratch (device globals; no allocations allowed) ----------
__device__ float  g_bufA[N_NODES * 128];
__device__ float  g_bufB[N_NODES * 128];
__device__ __half g_hT [128 * N_NODES];
__device__ __half g_Wt1[256 * 128];
__device__ __half g_Wt2[128 * 128];
__device__ __half g_Wt3[128 * 128];
__device__ __half g_Wt4[128 * 128];
__device__ float  g_src[N_NODES];
__device__ float  g_dst[N_NODES];
__device__ float  g_zA [N_NODES];
__device__ float  g_zB [N_NODES];
__device__ float  g_gmax[1];

__device__ __forceinline__ float leaky(float x) { return x >= 0.f ? x : ALPHA * x; }

__device__ __forceinline__ unsigned pack_h2(float lo, float hi) {
    unsigned r;
    asm("cvt.rn.f16x2.f32 %0, %1, %2;" : "=r"(r) : "f"(hi), "f"(lo));
    return r;
}

// ---------------------------------------------------------------------------
// mma.sync helpers (base-ISA HMMA path; validated in rounds 6-10)
// ---------------------------------------------------------------------------
__device__ __forceinline__ void ldsm_x4(unsigned& r0, unsigned& r1,
                                        unsigned& r2, unsigned& r3, unsigned a) {
    asm volatile("ldmatrix.sync.aligned.m8n8.x4.shared.b16 {%0,%1,%2,%3}, [%4];"
                 : "=r"(r0), "=r"(r1), "=r"(r2), "=r"(r3) : "r"(a));
}
__device__ __forceinline__ void mma16816(float* d,
                                         unsigned a0, unsigned a1, unsigned a2, unsigned a3,
                                         unsigned b0, unsigned b1) {
    asm volatile(
        "mma.sync.aligned.m16n8k16.row.col.f32.f16.f16.f32 "
        "{%0,%1,%2,%3}, {%4,%5,%6,%7}, {%8,%9}, {%0,%1,%2,%3};"
        : "+f"(d[0]), "+f"(d[1]), "+f"(d[2]), "+f"(d[3])
        : "r"(a0), "r"(a1), "r"(a2), "r"(a3), "r"(b0), "r"(b1));
}

// ---------------------------------------------------------------------------
// prep: W[k][n] f32 -> Wt[n][k] fp16 in global (192 KB total, L2-resident)
// ---------------------------------------------------------------------------
__global__ void __launch_bounds__(256) prep_kernel(
    const float* __restrict__ W1, const float* __restrict__ W2,
    const float* __restrict__ W3, const float* __restrict__ W4,
    __half* __restrict__ Wt1, __half* __restrict__ Wt2,
    __half* __restrict__ Wt3, __half* __restrict__ Wt4)
{
    int layer = blockIdx.y;
    int K = (layer == 0) ? 256 : 128;
    const float* W = (layer == 0) ? W1 : (layer == 1) ? W2 : (layer == 2) ? W3 : W4;
    __half* Wt     = (layer == 0) ? Wt1 : (layer == 1) ? Wt2 : (layer == 2) ? Wt3 : Wt4;
    int n = blockIdx.x;
    for (int k = threadIdx.x; k < K; k += 256)
        Wt[n * K + k] = __float2half_rn(W[(size_t)k * 128 + n]);
}

// ===========================================================================
// Fused MLP (4 layers) via HMMA, 64 rows/block, grid 128.
// W tiles double-buffered via cp.async from pre-transposed fp16 Wt (global),
// prefetching layer l+1 during layer l's mma.
// smem: WT0, WT1 [128][SW], act A0/A1 [64][SW]  (SW=280 halves, 560B rows)
// ===========================================================================
#define SW 280
#define WT_BYTES  (128 * SW * 2)
#define ACT_BYTES (64 * SW * 2)
#define MLP_SMEM  (2 * WT_BYTES + 2 * ACT_BYTES)

struct Frag { float a[8][4]; };

__device__ __forceinline__ void mlp_mma(Frag& fr, unsigned inA, unsigned WTb,
                                        int K, int wrow, int wcol, int lane)
{
    const unsigned a_base = inA + ((unsigned)(wrow + (lane & 15)) * SW
                          + (unsigned)((lane >> 4) * 8)) * 2;
    const unsigned b_base = WTb + ((unsigned)(wcol + (lane & 7) + ((lane >> 4) << 3)) * SW
                          + (unsigned)(((lane >> 3) & 1) << 3)) * 2;
#pragma unroll 4
    for (int ks = 0; ks < K / 16; ks++) {
        unsigned a0, a1, a2, a3;
        ldsm_x4(a0, a1, a2, a3, a_base + (unsigned)ks * 32);
#pragma unroll
        for (int nb = 0; nb < 4; nb++) {
            unsigned b0, b1, b2, b3;
            ldsm_x4(b0, b1, b2, b3,
                    b_base + (unsigned)nb * 16 * SW * 2 + (unsigned)ks * 32);
            mma16816(fr.a[nb * 2],     a0, a1, a2, a3, b0, b1);
            mma16816(fr.a[nb * 2 + 1], a0, a1, a2, a3, b2, b3);
        }
    }
}

__global__ void __launch_bounds__(256) mlp_kernel(
    const float* __restrict__ nodes,
    const __half* __restrict__ Wt1, const float* __restrict__ b1,
    const __half* __restrict__ Wt2, const float* __restrict__ b2,
    const __half* __restrict__ Wt3, const float* __restrict__ b3,
    const __half* __restrict__ Wt4, const float* __restrict__ b4,
    const float* __restrict__ a_w,
    __half* __restrict__ hT, float* __restrict__ s_src, float* __restrict__ s_dst)
{
    extern __shared__ char sm[];
    const unsigned smb = (unsigned)__cvta_generic_to_shared(sm);
    const unsigned WT0 = smb;
    const unsigned WT1 = smb + WT_BYTES;
    const unsigned A0  = smb + 2 * WT_BYTES;
    const unsigned A1  = A0 + ACT_BYTES;

    const int tid = threadIdx.x, wid = tid >> 5, lane = tid & 31;
    const int r0 = blockIdx.x * 64;
    const int wrow = (wid & 3) * 16;
    const int wcol = (wid >> 2) * 64;

    // cp.async loader: Wt[n][k] fp16 -> WTb rows n (stride SW*2), 16B chunks
    auto load_Wt = [&](const __half* Wtg, int kc_bits, unsigned WTb) {
        int iters = 1 << (kc_bits - 1);     // (128 << kc_bits) / 256
        for (int i = 0; i < iters; i++) {
            int idx = tid + i * 256;
            int kc = idx & ((1 << kc_bits) - 1);
            int n  = idx >> kc_bits;
            unsigned dst = WTb + (unsigned)n * (SW * 2) + (unsigned)kc * 16;
            const char* src = (const char*)Wtg + ((size_t)n << (kc_bits + 4)) + kc * 16;
            asm volatile("cp.async.ca.shared.global [%0], [%1], 16;"
                         :: "r"(dst), "l"(src));
        }
        asm volatile("cp.async.commit_group;" ::: "memory");
    };

    // W1 -> WT0 (async) while loading x
    load_Wt(Wt1, 5, WT0);

    // ---- load x (64 x 256 f32) -> act0 fp16 ----
#pragma unroll
    for (int i = 0; i < 16; i++) {
        int idx = tid + i * 256;
        int r = idx >> 6, c4 = (idx & 63) << 2;
        float4 v = *reinterpret_cast<const float4*>(&nodes[(size_t)(r0 + r) * 256 + c4]);
        unsigned h01 = pack_h2(v.x, v.y);
        unsigned h23 = pack_h2(v.z, v.w);
        unsigned ad = A0 + ((unsigned)r * SW + (unsigned)c4) * 2;
        asm volatile("st.shared.v2.b32 [%0], {%1,%2};" :: "r"(ad), "r"(h01), "r"(h23));
    }
    asm volatile("cp.async.wait_group 0;" ::: "memory");
    __syncthreads();

    // =============== layers 1-3 (relu), W(l+1) prefetched under mma(l) ======
    const __half* Wts[3] = { Wt2, Wt3, Wt4 };
    const float*  bs[3]  = { b1, b2, b3 };
#pragma unroll 1
    for (int l = 0; l < 3; l++) {
        const int K = (l == 0) ? 256 : 128;
        const unsigned inA  = (l & 1) ? A1 : A0;
        const unsigned outA = (l & 1) ? A0 : A1;
        const unsigned WTc  = (l & 1) ? WT1 : WT0;
        const unsigned WTn  = (l & 1) ? WT0 : WT1;

        load_Wt(Wts[l], 4, WTn);            // prefetch next layer's W

        Frag fr;
#pragma unroll
        for (int f = 0; f < 8; f++)
#pragma unroll
            for (int c = 0; c < 4; c++) fr.a[f][c] = 0.f;
        mlp_mma(fr, inA, WTc, K, wrow, wcol, lane);
        __syncthreads();                     // mma done before act overwrite

        const float* bias = bs[l];
        const int r1 = wrow + (lane >> 2);
#pragma unroll
        for (int f = 0; f < 8; f++) {
            int n0 = wcol + f * 8 + (lane & 3) * 2;
            float bx = bias[n0], by = bias[n0 + 1];
            float v0 = fmaxf(fr.a[f][0] + bx, 0.f);
            float v1 = fmaxf(fr.a[f][1] + by, 0.f);
            float v2 = fmaxf(fr.a[f][2] + bx, 0.f);
            float v3 = fmaxf(fr.a[f][3] + by, 0.f);
            unsigned p0 = pack_h2(v0, v1);
            unsigned p1 = pack_h2(v2, v3);
            unsigned ad0 = outA + ((unsigned)r1 * SW + (unsigned)n0) * 2;
            unsigned ad1 = outA + ((unsigned)(r1 + 8) * SW + (unsigned)n0) * 2;
            asm volatile("st.shared.u32 [%0], %1;" :: "r"(ad0), "r"(p0));
            asm volatile("st.shared.u32 [%0], %1;" :: "r"(ad1), "r"(p1));
        }
        asm volatile("cp.async.wait_group 0;" ::: "memory");
        __syncthreads();                     // next W + act visible
    }

    // =============== layer 4 (no relu) + fused scores + h store =============
    Frag fr;
#pragma unroll
    for (int f = 0; f < 8; f++)
#pragma unroll
        for (int c = 0; c < 4; c++) fr.a[f][c] = 0.f;
    mlp_mma(fr, A1, WT1, 128, wrow, wcol, lane);   // layer3 out = A1, W4 in WT1
    __syncthreads();

    const int r1 = wrow + (lane >> 2);
    float p1a = 0.f, p1b = 0.f, p2a = 0.f, p2b = 0.f;
#pragma unroll
    for (int f = 0; f < 8; f++) {
        int n0 = wcol + f * 8 + (lane & 3) * 2;
        float bx = b4[n0], by = b4[n0 + 1];
        float a1x = a_w[n0],       a1y = a_w[n0 + 1];
        float a2x = a_w[128 + n0], a2y = a_w[128 + n0 + 1];
        float v0 = fr.a[f][0] + bx, v1 = fr.a[f][1] + by;
        float v2 = fr.a[f][2] + bx, v3 = fr.a[f][3] + by;
        p1a += v0 * a1x + v1 * a1y;  p1b += v0 * a2x + v1 * a2y;
        p2a += v2 * a1x + v3 * a1y;  p2b += v2 * a2x + v3 * a2y;
        unsigned q0 = pack_h2(v0, v1);
        unsigned q1 = pack_h2(v2, v3);
        unsigned ad0 = A0 + ((unsigned)r1 * SW + (unsigned)n0) * 2;
        unsigned ad1 = A0 + ((unsigned)(r1 + 8) * SW + (unsigned)n0) * 2;
        asm volatile("st.shared.u32 [%0], %1;" :: "r"(ad0), "r"(q0));
        asm volatile("st.shared.u32 [%0], %1;" :: "r"(ad1), "r"(q1));
    }
#pragma unroll
    for (int o = 1; o < 4; o <<= 1) {
        p1a += __shfl_xor_sync(0xffffffffu, p1a, o);
        p1b += __shfl_xor_sync(0xffffffffu, p1b, o);
        p2a += __shfl_xor_sync(0xffffffffu, p2a, o);
        p2b += __shfl_xor_sync(0xffffffffu, p2b, o);
    }
    const int cg = wid >> 2;
    if ((lane & 3) == 0) {
        unsigned s0 = A1 + (unsigned)((r1 * 2 + cg) * 4);
        unsigned s1 = A1 + (unsigned)(((r1 + 8) * 2 + cg) * 4);
        unsigned d0 = A1 + 1024u + (unsigned)((r1 * 2 + cg) * 4);
        unsigned d1 = A1 + 1024u + (unsigned)(((r1 + 8) * 2 + cg) * 4);
        asm volatile("st.shared.f32 [%0], %1;" :: "r"(s0), "f"(p1a));
        asm volatile("st.shared.f32 [%0], %1;" :: "r"(s1), "f"(p2a));
        asm volatile("st.shared.f32 [%0], %1;" :: "r"(d0), "f"(p1b));
        asm volatile("st.shared.f32 [%0], %1;" :: "r"(d1), "f"(p2b));
    }
    __syncthreads();

    if (tid < 64) {
        float sa, sb, da, db;
        unsigned base = A1 + (unsigned)(tid * 8);
        asm volatile("ld.shared.f32 %0, [%1];"      : "=f"(sa) : "r"(base));
        asm volatile("ld.shared.f32 %0, [%1+4];"    : "=f"(sb) : "r"(base));
        asm volatile("ld.shared.f32 %0, [%1+1024];" : "=f"(da) : "r"(base));
        asm volatile("ld.shared.f32 %0, [%1+1028];" : "=f"(db) : "r"(base));
        s_src[r0 + tid] = sa + sb;
        s_dst[r0 + tid] = da + db;
    }

    // hT[c][r0 + seg*32 .. +31] from h fp16 in A0
    {
        int c = tid & 127, seg = tid >> 7;
        unsigned r16[16];
#pragma unroll
        for (int u = 0; u < 16; u++) {
            unsigned short h0, h1;
            unsigned ad = A0 + ((unsigned)(seg * 32 + u * 2) * SW + (unsigned)c) * 2;
            asm volatile("ld.shared.u16 %0, [%1];" : "=h"(h0) : "r"(ad));
            asm volatile("ld.shared.u16 %0, [%1];" : "=h"(h1) : "r"(ad + SW * 2));
            r16[u] = (unsigned)h0 | ((unsigned)h1 << 16);
        }
        uint4* dst = reinterpret_cast<uint4*>(&hT[(size_t)c * N_NODES + r0 + seg * 32]);
        dst[0] = make_uint4(r16[0],  r16[1],  r16[2],  r16[3]);
        dst[1] = make_uint4(r16[4],  r16[5],  r16[6],  r16[7]);
        dst[2] = make_uint4(r16[8],  r16[9],  r16[10], r16[11]);
        dst[3] = make_uint4(r16[12], r16[13], r16[14], r16[15]);
    }
}

// ---------------------------------------------------------------------------
// gmax
// ---------------------------------------------------------------------------
__global__ void __launch_bounds__(256) gmax_kernel(
    const float* __restrict__ s_dst, float* __restrict__ out)
{
    __shared__ float red[256];
    float m = -1e30f;
    for (int i = threadIdx.x; i < N_NODES; i += 256)
        m = fmaxf(m, s_dst[i]);
    red[threadIdx.x] = m;
    __syncthreads();
    for (int s = 128; s; s >>= 1) {
        if (threadIdx.x < s) red[threadIdx.x] = fmaxf(red[threadIdx.x], red[threadIdx.x + s]);
        __syncthreads();
    }
    if (threadIdx.x == 0) out[0] = red[0];
}

// ---------------------------------------------------------------------------
// Fused attention via dense HMMA.
// M=64 rows/block, 256 threads (8 warps), 104 KB smem -> 2 blocks/SM:
// one block's P-build overlaps the other's HMMA stream.
// Grid (2 j-halves, 128 row-blocks) = 256 blocks, all resident in one wave.
// ---------------------------------------------------------------------------
#define NTILES 32
#define LDH 136
#define HTB (128 * LDH * 2)     // 34816
#define PB  (64 * LDH * 2)      // 17408
#define ATTN_SMEM (2 * HTB + 2 * PB)

__global__ void __launch_bounds__(256, 2) attn_kernel(
    const float* __restrict__ adj, const __half* __restrict__ hTg,
    const float* __restrict__ s_src, const float* __restrict__ s_dst,
    const float* __restrict__ p_ab, const float* __restrict__ p_gmax,
    float* __restrict__ accA, float* __restrict__ accB,
    float* __restrict__ zA, float* __restrict__ zB)
{
    extern __shared__ char sm[];
    const unsigned smb = (unsigned)__cvta_generic_to_shared(sm);
    const unsigned HT0 = smb, HT1 = smb + HTB;
    const unsigned P0 = smb + 2 * HTB, P1 = smb + 2 * HTB + PB;

    const int tid = threadIdx.x, wid = tid >> 5, lane = tid & 31;
    const int half = blockIdx.x, r0 = blockIdx.y * 64;
    const int j0 = half * (N_NODES / 2);
    float* accbuf = half ? accB : accA;
    float* zbuf   = half ? zB  : zA;

    const float ab   = *p_ab;
    const float gmax = *p_gmax;

    float si8[8], mi8[8], zv[8];
#pragma unroll
    for (int v = 0; v < 8; v++) {
        float sv = s_src[r0 + 8 * wid + v];
        si8[v] = sv;
        mi8[v] = leaky(sv + ab + gmax);
        zv[v] = 0.f;
    }

    // mma warp tiling: 4 row-groups x 2 col-groups; warp = 16 rows x 64 cols
    const int wrow = (wid & 3) * 16;
    const int wcol = (wid >> 2) * 64;
    const unsigned a_off = (unsigned)(wrow + (lane & 15)) * (LDH * 2)
                         + (unsigned)((lane >> 4) * 8) * 2;
    const unsigned b_off = (unsigned)(wcol + (lane & 7) + ((lane >> 4) << 3)) * (LDH * 2)
                         + (unsigned)(((lane >> 3) & 1) << 3) * 2;

    float acc[8][4];
#pragma unroll
    for (int f = 0; f < 8; f++)
#pragma unroll
        for (int c = 0; c < 4; c++) acc[f][c] = 0.f;

    const float* abase = adj + (size_t)(r0 + 8 * wid) * N_NODES + j0 + lane * 4;

    auto load_hT = [&](int tile, unsigned Hb) {
#pragma unroll
        for (int i = 0; i < 8; i++) {
            int ch = tid + i * 256;
            int c = ch >> 4, u = ch & 15;
            const __half* src = hTg + (size_t)c * N_NODES + j0 + tile * 128 + u * 8;
            unsigned ad = Hb + (unsigned)c * (LDH * 2) + (unsigned)u * 16;
            asm volatile("cp.async.ca.shared.global [%0], [%1], 16;"
                         :: "r"(ad), "l"(src));
        }
    };

    float4 av[8];
    load_hT(0, HT0);
    asm volatile("cp.async.commit_group;" ::: "memory");
#pragma unroll
    for (int v = 0; v < 8; v++)
        av[v] = *reinterpret_cast<const float4*>(abase + (size_t)v * N_NODES);

    for (int k = 0; k < NTILES; k++) {
        const unsigned Pb = (k & 1) ? P1 : P0;
        const unsigned Hb = (k & 1) ? HT1 : HT0;

        // build P(k): each lane writes its 4-j chunk of 8 rows
        float4 t = *reinterpret_cast<const float4*>(s_dst + j0 + k * 128 + lane * 4);
#pragma unroll
        for (int v = 0; v < 8; v++) {
            float4 a = av[v];
            unsigned lo = 0u, hi = 0u;
            if (a.x >= 0.5f) { float w = __expf(leaky(si8[v] + t.x + ab) - mi8[v]);
                zv[v] += w; lo  = (unsigned)__half_as_ushort(__float2half_rn(w)); }
            if (a.y >= 0.5f) { float w = __expf(leaky(si8[v] + t.y + ab) - mi8[v]);
                zv[v] += w; lo |= (unsigned)__half_as_ushort(__float2half_rn(w)) << 16; }
            if (a.z >= 0.5f) { float w = __expf(leaky(si8[v] + t.z + ab) - mi8[v]);
                zv[v] += w; hi  = (unsigned)__half_as_ushort(__float2half_rn(w)); }
            if (a.w >= 0.5f) { float w = __expf(leaky(si8[v] + t.w + ab) - mi8[v]);
                zv[v] += w; hi |= (unsigned)__half_as_ushort(__float2half_rn(w)) << 16; }
            unsigned ad = Pb + (unsigned)(8 * wid + v) * (LDH * 2) + (unsigned)lane * 8;
            asm volatile("st.shared.v2.b32 [%0], {%1,%2};"
                         :: "r"(ad), "r"(lo), "r"(hi) : "memory");
        }

        asm volatile("cp.async.wait_group 0;" ::: "memory");
        __syncthreads();

        if (k + 1 < NTILES) {
            load_hT(k + 1, (k & 1) ? HT0 : HT1);
            asm volatile("cp.async.commit_group;" ::: "memory");
#pragma unroll
            for (int v = 0; v < 8; v++)
                av[v] = *reinterpret_cast<const float4*>(
                    abase + (size_t)v * N_NODES + (k + 1) * 128);
        }

#pragma unroll
        for (int ks = 0; ks < 8; ks++) {
            unsigned a0, a1, a2, a3;
            ldsm_x4(a0, a1, a2, a3, Pb + a_off + (unsigned)ks * 32);
#pragma unroll
            for (int nb = 0; nb < 4; nb++) {
                unsigned b0, b1, b2, b3;
                ldsm_x4(b0, b1, b2, b3,
                        Hb + b_off + (unsigned)nb * 16 * (LDH * 2) + (unsigned)ks * 32);
                mma16816(acc[nb * 2],     a0, a1, a2, a3, b0, b1);
                mma16816(acc[nb * 2 + 1], a0, a1, a2, a3, b2, b3);
            }
        }
    }

#pragma unroll
    for (int f = 0; f < 8; f++) {
        int n0 = wcol + f * 8 + (lane & 3) * 2;
        int rr = r0 + wrow + (lane >> 2);
        *reinterpret_cast<float2*>(&accbuf[(size_t)rr * 128 + n0]) =
            make_float2(acc[f][0], acc[f][1]);
        *reinterpret_cast<float2*>(&accbuf[(size_t)(rr + 8) * 128 + n0]) =
            make_float2(acc[f][2], acc[f][3]);
    }
#pragma unroll
    for (int v = 0; v < 8; v++) {
        float zz = zv[v];
#pragma unroll
        for (int o = 16; o; o >>= 1)
            zz += __shfl_xor_sync(0xffffffffu, zz, o);
        if (lane == 0) zbuf[r0 + 8 * wid + v] = zz;
    }
}

// ---------------------------------------------------------------------------
// out = leaky((accA + accB) / (zA + zB))
// ---------------------------------------------------------------------------
__global__ void __launch_bounds__(256) combine_kernel(
    const float* __restrict__ a, const float* __restrict__ b,
    const float* __restrict__ za, const float* __restrict__ zb,
    float* __restrict__ out)
{
    int idx = blockIdx.x * 256 + threadIdx.x;
    int row = idx >> 5;
    float inv = 1.f / (za[row] + zb[row]);
    float4 x = reinterpret_cast<const float4*>(a)[idx];
    float4 y = reinterpret_cast<const float4*>(b)[idx];
    float4 o;
    o.x = leaky((x.x + y.x) * inv);
    o.y = leaky((x.y + y.y) * inv);
    o.z = leaky((x.z + y.z) * inv);
    o.w = leaky((x.w + y.w) * inv);
    reinterpret_cast<float4*>(out)[idx] = o;
}

// ---------------------------------------------------------------------------
extern "C" void kernel_launch(void* const* d_in, const int* in_sizes, int n_in,
                              void* d_out, int out_size)
{
    const float* nodes = (const float*)d_in[0];
    const float* adj   = (const float*)d_in[1];
    const float* W1    = (const float*)d_in[2];
    const float* b1    = (const float*)d_in[3];
    const float* W2    = (const float*)d_in[4];
    const float* b2    = (const float*)d_in[5];
    const float* W3    = (const float*)d_in[6];
    const float* b3    = (const float*)d_in[7];
    const float* W4    = (const float*)d_in[8];
    const float* b4    = (const float*)d_in[9];
    const float* a_w   = (const float*)d_in[10];
    const float* a_b   = (const float*)d_in[11];
    float* out = (float*)d_out;

    float *pA, *pB, *pSrc, *pDst, *pZA, *pZB, *pGM;
    __half *pHT, *pW1, *pW2, *pW3, *pW4;
    cudaGetSymbolAddress((void**)&pA,  g_bufA);
    cudaGetSymbolAddress((void**)&pB,  g_bufB);
    cudaGetSymbolAddress((void**)&pHT, g_hT);
    cudaGetSymbolAddress((void**)&pW1, g_Wt1);
    cudaGetSymbolAddress((void**)&pW2, g_Wt2);
    cudaGetSymbolAddress((void**)&pW3, g_Wt3);
    cudaGetSymbolAddress((void**)&pW4, g_Wt4);
    cudaGetSymbolAddress((void**)&pSrc, g_src);
    cudaGetSymbolAddress((void**)&pDst, g_dst);
    cudaGetSymbolAddress((void**)&pZA, g_zA);
    cudaGetSymbolAddress((void**)&pZB, g_zB);
    cudaGetSymbolAddress((void**)&pGM, g_gmax);

    cudaFuncSetAttribute(mlp_kernel,
                         cudaFuncAttributeMaxDynamicSharedMemorySize, MLP_SMEM);
    cudaFuncSetAttribute(attn_kernel,
                         cudaFuncAttributeMaxDynamicSharedMemorySize, ATTN_SMEM);

    // pre-transpose weights to fp16 (L2-resident)
    prep_kernel<<<dim3(128, 4), 256>>>(W1, W2, W3, W4, pW1, pW2, pW3, pW4);
    // fused 4-layer MLP + scores + hT (cp.async double-buffered W)
    mlp_kernel<<<128, 256, MLP_SMEM>>>(nodes, pW1, b1, pW2, b2, pW3, b3, pW4, b4,
                                       a_w, pHT, pSrc, pDst);
    // global max bound
    gmax_kernel<<<1, 256>>>(pDst, pGM);
    // fused attention via dense HMMA (2 blocks/SM)
    dim3 agrid(2, 128);
    attn_kernel<<<agrid, 256, ATTN_SMEM>>>(
        adj, pHT, pSrc, pDst, a_b, pGM, pA, pB, pZA, pZB);
    // normalize + activation
    combine_kernel<<<1024, 256>>>(pA, pB, pZA, pZB, out);
}